// round 13
// baseline (speedup 1.0000x reference)
#include <cuda_runtime.h>
#include <cuda_bf16.h>
#include <math.h>
#include <stdint.h>

// Problem constants
#define Bn   128
#define Ln   200
#define Dn   128
#define Hn   8
#define DKn  16
#define FFn  512
#define NLn  2
#define NWn  3
#define Mn   (Bn*Ln)          // 25600
#define BWn  (Bn*NWn)         // 384
#define MWn  (BWn*Ln)         // 76800

typedef unsigned long long u64t;

// ---- packed f32x2 helpers (per-lane IEEE fp32) ----------------------------
__device__ __forceinline__ u64t pk2(float lo, float hi)
{
    u64t r; asm("mov.b64 %0, {%1,%2};" : "=l"(r) : "f"(lo), "f"(hi)); return r;
}
__device__ __forceinline__ float2 upk2(u64t v)
{
    float2 r; asm("mov.b64 {%0,%1}, %2;" : "=f"(r.x), "=f"(r.y) : "l"(v)); return r;
}
#define FMA2(d, a, b) \
    asm("fma.rn.f32x2 %0, %1, %2, %3;" : "=l"(d) : "l"(a), "l"(b), "l"(d))

// ---- XLA tanh replica (llvm_ir::EmitFastTanh, with_fma=true) --------------
__device__ __forceinline__ float xla_tanh(float x)
{
    float ax = fabsf(x);
    if (ax < 0.0004f) return x;
    const float clampv = 7.99881172180175781f;
    float xc = fminf(fmaxf(x, -clampv), clampv);
    float x2 = xc * xc;
    float p = fmaf(x2, -2.76076847742355e-16f, 2.00018790482477e-13f);
    p = fmaf(x2, p, -8.60467152213735e-11f);
    p = fmaf(x2, p, 5.12229709037114e-08f);
    p = fmaf(x2, p, 1.48572235717979e-05f);
    p = fmaf(x2, p, 6.37261928875436e-04f);
    p = fmaf(x2, p, 4.89352455891786e-03f);
    p = xc * p;
    float q = fmaf(x2, 1.19825839466702e-06f, 1.18534705686654e-04f);
    q = fmaf(x2, q, 2.26843463243900e-03f);
    q = fmaf(x2, q, 4.89352518554385e-03f);
    return p / q;
}

// ---------------- scratch (device globals; allocation-free) ----------------
__device__ float  g_h[Mn*Dn];
__device__ float  g_x[Mn*Dn];
__device__ float  g_qkv[Mn*384];
__device__ float  g_att[Mn*Dn];
__device__ float  g_ff[Mn*FFn];
__device__ float  g_mixed[MWn*Dn];
__device__ float  g_hWnode[MWn*384];
__device__ float  g_hWstep[MWn*Dn];
__device__ float  g_mmean[BWn*Dn];
__device__ float  g_fixedW[BWn*Dn];
__device__ float  g_Wqkv[2*Dn*384];
__device__ double g_dpart[200*128];
__device__ double g_dmean[128];
__device__ float  g_bnm[128];
__device__ float  g_bninv[128];
__device__ float  g_coef[4];

// ---------------- SGEMM 128x128 tile, 8x8 microtile, f32x2 FMA -------------
// flags: 1=+bias[n], 2=relu, 4=+res[m*N+n]   (bit-identical k-order)
__global__ void __launch_bounds__(256) sgemm_k(
    const float* __restrict__ A, const float* __restrict__ B,
    const float* __restrict__ bias, const float* __restrict__ res,
    float* __restrict__ C, int M, int N, int K, int flags)
{
    __shared__ float As[16][130];
    __shared__ float Bs[16][128];
    int tid = threadIdx.x;
    int m0 = blockIdx.y * 128, n0 = blockIdx.x * 128;
    int ty = tid >> 4;              // 0..15 -> 8-row group
    int tx = tid & 15;              // 0..15 -> 8-col group
    u64t acc2[8][4] = {};
    for (int k0 = 0; k0 < K; k0 += 16) {
#pragma unroll
        for (int j = 0; j < 2; j++) {
            int f = tid + 256 * j;
            int row = f >> 2, c4 = (f & 3) << 2;
            float4 av = *(const float4*)&A[(size_t)(m0 + row) * K + k0 + c4];
            As[c4 + 0][row] = av.x; As[c4 + 1][row] = av.y;
            As[c4 + 2][row] = av.z; As[c4 + 3][row] = av.w;
        }
#pragma unroll
        for (int j = 0; j < 2; j++) {
            int f = tid + 256 * j;
            int brow = f >> 5, bcol = (f & 31) << 2;
            *(float4*)&Bs[brow][bcol] =
                *(const float4*)&B[(size_t)(k0 + brow) * N + n0 + bcol];
        }
        __syncthreads();
#pragma unroll
        for (int kk = 0; kk < 16; kk++) {
            float a[8];
#pragma unroll
            for (int i = 0; i < 8; i++) a[i] = As[kk][ty * 8 + i];
            u64t b[4];
#pragma unroll
            for (int j = 0; j < 4; j++) b[j] = *(const u64t*)&Bs[kk][tx * 8 + 2 * j];
#pragma unroll
            for (int i = 0; i < 8; i++) {
                u64t aa = pk2(a[i], a[i]);
#pragma unroll
                for (int j = 0; j < 4; j++) FMA2(acc2[i][j], aa, b[j]);
            }
        }
        __syncthreads();
    }
#pragma unroll
    for (int i = 0; i < 8; i++) {
        int m = m0 + ty * 8 + i;
#pragma unroll
        for (int j = 0; j < 4; j++) {
            float2 v2 = upk2(acc2[i][j]);
            float vv[2] = {v2.x, v2.y};
#pragma unroll
            for (int u = 0; u < 2; u++) {
                int n = n0 + tx * 8 + 2 * j + u;
                float v = vv[u];
                if (flags & 1) v += bias[n];
                if (flags & 4) v += res[(size_t)m * N + n];
                if (flags & 2) v = fmaxf(v, 0.f);
                C[(size_t)m * N + n] = v;
            }
        }
    }
}

// ---------------- weight repack: Wqkv[l][d][h*16+k] ------------------------
__global__ void repack_k(const float* __restrict__ Wq, const float* __restrict__ Wk,
                         const float* __restrict__ Wv, float* __restrict__ Wqkv)
{
    int i = blockIdx.x * blockDim.x + threadIdx.x;
    if (i >= 2 * Hn * Dn * DKn) return;
    int kk = i % DKn;
    int d  = (i / DKn) % Dn;
    int hh = (i / (DKn * Dn)) % Hn;
    int l  = i / (DKn * Dn * Hn);
    int src = ((l * Hn + hh) * Dn + d) * DKn + kk;
    float* o = Wqkv + (size_t)l * Dn * 384 + (size_t)d * 384;
    o[hh * 16 + kk]        = Wq[src];
    o[128 + hh * 16 + kk]  = Wk[src];
    o[256 + hh * 16 + kk]  = Wv[src];
}

// ---------------- init embed: h = input@init_W + init_b --------------------
__global__ void init_k(const float* __restrict__ inp, const float* __restrict__ W,
                       const float* __restrict__ bv, float* __restrict__ h)
{
    int m = blockIdx.x, d = threadIdx.x;
    float4 iv = *(const float4*)&inp[(size_t)m * 4];
    float s = iv.x * W[d];
    s = fmaf(iv.y, W[128 + d], s);
    s = fmaf(iv.z, W[256 + d], s);
    s = fmaf(iv.w, W[384 + d], s);
    h[(size_t)m * Dn + d] = s + bv[d];
}

// ---------------- encoder attention: padded smem, 2 CTAs/SM ----------------
__global__ void __launch_bounds__(256, 2) attn_k(const float* __restrict__ qkv,
                                                 float* __restrict__ outp)
{
    __shared__ float sq[Ln][17], sk[Ln][17], sv[Ln][17];
    int b = blockIdx.x >> 3, hh = blockIdx.x & 7;
    int tid = threadIdx.x, ln = tid & 31, wp = tid >> 5;
    for (int idx = tid; idx < Ln * 4; idx += 256) {
        int n = idx >> 2, k4 = (idx & 3) << 2;
        const float* row = qkv + ((size_t)(b * Ln + n)) * 384 + hh * 16 + k4;
        float4 q4 = *(const float4*)row;
        float4 k4v = *(const float4*)(row + 128);
        float4 v4 = *(const float4*)(row + 256);
        sq[n][k4 + 0] = q4.x; sq[n][k4 + 1] = q4.y; sq[n][k4 + 2] = q4.z; sq[n][k4 + 3] = q4.w;
        sk[n][k4 + 0] = k4v.x; sk[n][k4 + 1] = k4v.y; sk[n][k4 + 2] = k4v.z; sk[n][k4 + 3] = k4v.w;
        sv[n][k4 + 0] = v4.x; sv[n][k4 + 1] = v4.y; sv[n][k4 + 2] = v4.z; sv[n][k4 + 3] = v4.w;
    }
    __syncthreads();
    for (int n = wp; n < Ln; n += 8) {
        float qr[16];
#pragma unroll
        for (int kk = 0; kk < 16; kk++) qr[kk] = sq[n][kk];
        float sc[7]; float mx = -3.4e38f;
#pragma unroll
        for (int i = 0; i < 7; i++) {
            int m = ln + 32 * i;
            if (m < Ln) {
                float s = 0.f;
#pragma unroll
                for (int kk = 0; kk < 16; kk++) s = fmaf(qr[kk], sk[m][kk], s);
                s *= 0.25f; sc[i] = s; mx = fmaxf(mx, s);
            } else sc[i] = -3.4e38f;
        }
#pragma unroll
        for (int o = 16; o > 0; o >>= 1) mx = fmaxf(mx, __shfl_xor_sync(0xffffffffu, mx, o));
        float se = 0.f;
#pragma unroll
        for (int i = 0; i < 7; i++) {
            int m = ln + 32 * i;
            if (m < Ln) { sc[i] = expf(sc[i] - mx); se += sc[i]; }
        }
#pragma unroll
        for (int o = 16; o > 0; o >>= 1) se += __shfl_xor_sync(0xffffffffu, se, o);
        float inv = 1.f / se;
        float ps[7];
#pragma unroll
        for (int i = 0; i < 7; i++) ps[i] = sc[i] * inv;
#pragma unroll
        for (int kk = 0; kk < 16; kk++) {
            float a = 0.f;
#pragma unroll
            for (int i = 0; i < 7; i++) {
                int m = ln + 32 * i;
                if (m < Ln) a = fmaf(ps[i], sv[m][kk], a);
            }
#pragma unroll
            for (int o = 16; o > 0; o >>= 1) a += __shfl_xor_sync(0xffffffffu, a, o);
            if (ln == 0) outp[((size_t)(b * Ln + n)) * Dn + hh * 16 + kk] = a;
        }
    }
}

// ---------------- batch-norm: two-pass, double stats -----------------------
__global__ void bnsum_k(const float* __restrict__ x, double* __restrict__ part)
{
    int d = threadIdx.x; int blk = blockIdx.x;
    const float* p = x + (size_t)blk * 128 * Dn + d;
    double s = 0.0;
    for (int r = 0; r < 128; r++) s += (double)p[(size_t)r * Dn];
    part[blk * 128 + d] = s;
}
__global__ void bnmean_k(const double* __restrict__ part, double* __restrict__ dmean,
                         float* __restrict__ bnm)
{
    int d = threadIdx.x;
    double s = 0.0;
    for (int i = 0; i < 200; i++) s += part[i * 128 + d];
    double m = s / 25600.0;
    dmean[d] = m;
    bnm[d] = (float)m;
}
__global__ void bnsq_k(const float* __restrict__ x, const double* __restrict__ dmean,
                       double* __restrict__ part)
{
    int d = threadIdx.x; int blk = blockIdx.x;
    double m = dmean[d];
    const float* p = x + (size_t)blk * 128 * Dn + d;
    double s = 0.0;
    for (int r = 0; r < 128; r++) { double dv = (double)p[(size_t)r * Dn] - m; s += dv * dv; }
    part[blk * 128 + d] = s;
}
__global__ void bnvar_k(const double* __restrict__ part, float* __restrict__ bninv)
{
    int d = threadIdx.x;
    double s = 0.0;
    for (int i = 0; i < 200; i++) s += part[i * 128 + d];
    float var = (float)(s / 25600.0);
    bninv[d] = rsqrtf(var + 1e-5f);
}
__global__ void bnapply_k(const float* __restrict__ bnm, const float* __restrict__ bninv,
                          const float* __restrict__ x,
                          const float* __restrict__ g, const float* __restrict__ bb,
                          float* __restrict__ y, int total)
{
    int i = blockIdx.x * blockDim.x + threadIdx.x;
    if (i >= total) return;
    int d = i & 127;
    y[i] = (x[i] - bnm[d]) * bninv[d] * g[d] + bb[d];
}

// ---------------- routing net → coef ---------------------------------------
__global__ void routing_k(const float* __restrict__ w_in, const float* __restrict__ embW,
                          const float* __restrict__ embB, const float* __restrict__ outW,
                          const float* __restrict__ outB, float* __restrict__ coef)
{
    __shared__ double red[3][128];
    int d = threadIdx.x;
    for (int w = 0; w < NWn; w++) {
        float a = w_in[w * 2 + 0] * embW[d];
        a = fmaf(w_in[w * 2 + 1], embW[128 + d], a);
        a = a + embB[d];
        a = fmaxf(a, 0.f);
        red[w][d] = (double)a * (double)outW[d * 3];
    }
    __syncthreads();
    for (int s = 64; s > 0; s >>= 1) {
        if (d < s) for (int w = 0; w < NWn; w++) red[w][d] += red[w][d + s];
        __syncthreads();
    }
    if (d < NWn) {
        float v = (float)red[d][0] + outB[0] + w_in[d * 2 + 0];
        coef[d] = xla_tanh(v);
    }
}

// ---------------- mixed = coef_w * h ----------------------------------------
__global__ void mixscale_k(const float* __restrict__ h, const float* __restrict__ coef,
                           float* __restrict__ mixed)
{
    int row = blockIdx.x;
    int d = threadIdx.x;
    int bwIdx = row / Ln, n = row % Ln;
    int b = bwIdx / NWn, w = bwIdx % NWn;
    mixed[(size_t)row * Dn + d] = coef[w] * h[((size_t)(b * Ln + n)) * Dn + d];
}

// ---------------- mean over nodes of mixed ---------------------------------
__global__ void mmean_k(const float* __restrict__ mixed, float* __restrict__ mm)
{
    int bw = blockIdx.x, d = threadIdx.x;
    double s = 0.0;
    for (int n = 0; n < Ln; n++) s += (double)mixed[((size_t)(bw * Ln + n)) * Dn + d];
    mm[bw * Dn + d] = (float)(s / 200.0);
}

// ---------------- persistent decode: one CTA per bw, 2 CTAs/SM -------------
#define SMEM_DECODE ((25600 + 1600 + 128 + 512 + 200 + 128 + 128 + 128) * 4 + 224)

__global__ void __launch_bounds__(256, 2) decode_k(
    const float* __restrict__ hWnode, const float* __restrict__ hWstep,
    const float* __restrict__ fixedW, const float* __restrict__ Wout,
    float* __restrict__ out, int writeLog, long long pisOff)
{
    extern __shared__ float sm[];
    float* gKT    = sm;                 // [128][200] transposed gK
    float* scomp  = gKT + 128 * 200;    // [8][200] softmax probs
    float* sq     = scomp + 1600;       // [128] query
    float* spart  = sq + 128;           // [512] partials
    float* slog   = spart + 512;        // [200] logits (own buffer)
    float* sheads = slog + 200;         // [128]
    float* sglim  = sheads + 128;       // [128]
    float* sfix   = sglim + 128;        // [128]
    unsigned char* svis = (unsigned char*)(sfix + 128); // [200]
    float2* spart2  = (float2*)spart;
    float2* sheads2 = (float2*)sheads;
    float2* sglim2  = (float2*)sglim;

    const int bw = blockIdx.x;
    const int tid = threadIdx.x;
    const int ln = tid & 31, wp = tid >> 5;
    const float* gVg = hWnode + ((size_t)bw * Ln) * 384 + 128;   // gV rows, stride 384

    for (int idx = tid; idx < Ln * 32; idx += 256) {
        int n = idx >> 5, c4 = (idx & 31) << 2;
        const float* row = hWnode + ((size_t)(bw * Ln + n)) * 384;
        float4 kv = *(const float4*)(row + c4);
        gKT[(c4 + 0) * 200 + n] = kv.x;
        gKT[(c4 + 1) * 200 + n] = kv.y;
        gKT[(c4 + 2) * 200 + n] = kv.z;
        gKT[(c4 + 3) * 200 + n] = kv.w;
    }
    if (tid < 128) sfix[tid] = fixedW[bw * Dn + tid];
    for (int idx = tid; idx < 200; idx += 256) svis[idx] = 0;
    __syncthreads();
    // initial query (prev = 0)
    if (tid < 128)
        sq[tid] = sfix[tid] + hWstep[((size_t)(bw * Ln)) * Dn + tid];
    __syncthreads();

    for (int t = 0; t < Ln; t++) {
        // 1. compat + masked softmax: warp wp = head hh
        {
            int hh = wp;
            float qr[16];
#pragma unroll
            for (int kk = 0; kk < 16; kk++) qr[kk] = sq[hh * 16 + kk];
            float cv[7]; float mx = -3.4e38f;
#pragma unroll
            for (int i = 0; i < 7; i++) {
                int n = ln + 32 * i;
                float c;
                if (n < Ln) {
                    float s = 0.f;
#pragma unroll
                    for (int kk = 0; kk < 16; kk++)
                        s = fmaf(qr[kk], gKT[(hh * 16 + kk) * 200 + n], s);
                    s = s * 0.25f;
                    c = svis[n] ? -1e9f : s;
                    mx = fmaxf(mx, c);
                } else c = -3.4e38f;
                cv[i] = c;
            }
#pragma unroll
            for (int o = 16; o > 0; o >>= 1) mx = fmaxf(mx, __shfl_xor_sync(0xffffffffu, mx, o));
            float se = 0.f;
#pragma unroll
            for (int i = 0; i < 7; i++) {
                int n = ln + 32 * i;
                if (n < Ln) { cv[i] = expf(cv[i] - mx); se += cv[i]; }
            }
#pragma unroll
            for (int o = 16; o > 0; o >>= 1) se += __shfl_xor_sync(0xffffffffu, se, o);
#pragma unroll
            for (int i = 0; i < 7; i++) {
                int n = ln + 32 * i;
                if (n < Ln) scomp[hh * 200 + n] = cv[i] / se;
            }
        }
        __syncthreads();
        // 2. heads: 4-way n split, skip p==0 (bit-exact; saves load + FMA)
        {
            int cp = tid & 63, q = tid >> 6;
            int hh = cp >> 3;
            const float* p = &scomp[hh * 200];
            int nb = q * 50;
            const float* gvrow = gVg + (size_t)nb * 384 + 2 * cp;
            u64t acc0 = 0ull, acc1 = 0ull;
#pragma unroll 5
            for (int n = 0; n < 50; n += 2) {
                float p0 = p[nb + n], p1 = p[nb + n + 1];
                if (p0 != 0.f) {
                    u64t g0 = *(const u64t*)(gvrow + (size_t)n * 384);
                    FMA2(acc0, pk2(p0, p0), g0);
                }
                if (p1 != 0.f) {
                    u64t g1 = *(const u64t*)(gvrow + (size_t)(n + 1) * 384);
                    FMA2(acc1, pk2(p1, p1), g1);
                }
            }
            float2 a0 = upk2(acc0), a1 = upk2(acc1);
            spart2[q * 64 + cp] = make_float2(a0.x + a1.x, a0.y + a1.y);
        }
        __syncthreads();
        if (tid < 64) {
            float2 x0 = spart2[tid], x1 = spart2[64 + tid];
            float2 x2 = spart2[128 + tid], x3 = spart2[192 + tid];
            sheads2[tid] = make_float2((x0.x + x1.x) + (x2.x + x3.x),
                                       (x0.y + x1.y) + (x2.y + x3.y));
        }
        __syncthreads();
        // 3. glimpse = heads @ Wout: 4-way c split
        {
            int dp = tid & 63, q = tid >> 6;
            int cb = q * 32;
            u64t acc0 = 0ull, acc1 = 0ull;
#pragma unroll 4
            for (int c = 0; c < 32; c += 2) {
                float h0 = sheads[cb + c], h1 = sheads[cb + c + 1];
                u64t w0 = *(const u64t*)&Wout[(size_t)(cb + c) * 128 + 2 * dp];
                u64t w1 = *(const u64t*)&Wout[(size_t)(cb + c + 1) * 128 + 2 * dp];
                FMA2(acc0, pk2(h0, h0), w0);
                FMA2(acc1, pk2(h1, h1), w1);
            }
            float2 a0 = upk2(acc0), a1 = upk2(acc1);
            spart2[q * 64 + dp] = make_float2(a0.x + a1.x, a0.y + a1.y);
        }
        __syncthreads();
        if (tid < 64) {
            float2 x0 = spart2[tid], x1 = spart2[64 + tid];
            float2 x2 = spart2[128 + tid], x3 = spart2[192 + tid];
            sglim2[tid] = make_float2((x0.x + x1.x) + (x2.x + x3.x),
                                      (x0.y + x1.y) + (x2.y + x3.y));
        }
        __syncthreads();
        // 4. logits: 4 n per warp (8-lane groups); loads skipped for visited,
        //    shuffles UNCONDITIONAL (all 32 lanes; R11 deadlock lesson)
        {
            int grp = ln >> 3, li = ln & 7;
#pragma unroll
            for (int r = 0; r < 7; r++) {
                int n = r * 32 + wp * 4 + grp;          // warp-uniform n<Ln status
                if (n < Ln) {
                    float s = 0.f;
                    if (!svis[n]) {
                        const float* lk = hWnode + ((size_t)(bw * Ln + n)) * 384 + 256 + li * 16;
                        const float* gl = sglim + li * 16;
#pragma unroll
                        for (int j = 0; j < 4; j++) {
                            float4 kv = *(const float4*)(lk + 4 * j);
                            s = fmaf(gl[4 * j + 0], kv.x, s);
                            s = fmaf(gl[4 * j + 1], kv.y, s);
                            s = fmaf(gl[4 * j + 2], kv.z, s);
                            s = fmaf(gl[4 * j + 3], kv.w, s);
                        }
                    }
                    s += __shfl_xor_sync(0xffffffffu, s, 4);
                    s += __shfl_xor_sync(0xffffffffu, s, 2);
                    s += __shfl_xor_sync(0xffffffffu, s, 1);
                    if (li == 0)
                        slog[n] = svis[n] ? -1e9f
                                          : xla_tanh(s * 0.08838834764831843f) * 10.f;
                }
            }
        }
        __syncthreads();
        // 5. redundant per-warp LSE + argmax (identical in every warp)
        float mx, lg_se; int bi;
        {
            float vals[7]; mx = -3.4e38f;
#pragma unroll
            for (int i = 0; i < 7; i++) {
                int n = ln + 32 * i;
                float v = (n < Ln) ? slog[n] : -3.4e38f;
                vals[i] = v;
                mx = fmaxf(mx, v);
            }
#pragma unroll
            for (int o = 16; o > 0; o >>= 1) mx = fmaxf(mx, __shfl_xor_sync(0xffffffffu, mx, o));
            float se = 0.f;
#pragma unroll
            for (int i = 0; i < 7; i++) {
                int n = ln + 32 * i;
                if (n < Ln) se += expf(vals[i] - mx);
            }
#pragma unroll
            for (int o = 16; o > 0; o >>= 1) se += __shfl_xor_sync(0xffffffffu, se, o);
            lg_se = logf(se);
            float bv = -3.4e38f; bi = 0x7fffffff;
#pragma unroll
            for (int i = 0; i < 7; i++) {
                int n = ln + 32 * i;
                if (n < Ln) {
                    float lp = (vals[i] - mx) - lg_se;
                    if (lp > bv || (lp == bv && n < bi)) { bv = lp; bi = n; }
                }
            }
#pragma unroll
            for (int o = 16; o > 0; o >>= 1) {
                float ov = __shfl_xor_sync(0xffffffffu, bv, o);
                int   oi = __shfl_xor_sync(0xffffffffu, bi, o);
                if (ov > bv || (ov == bv && oi < bi)) { bv = ov; bi = oi; }
            }
        }
        // 6. immediate writes (no barrier: every thread has mx/lg_se/bi)
        if (tid == 0) {
            svis[bi] = 1;
            if (pisOff >= 0)
                out[(size_t)pisOff + (size_t)bw * 200 + t] = (float)bi;
        }
        if (writeLog) {
            size_t base = ((size_t)bw * 200 + t) * 200;
            for (int n = tid; n < Ln; n += 256)
                out[base + n] = (slog[n] - mx) - lg_se;
        }
        if (tid < 128)
            sq[tid] = sfix[tid] + hWstep[((size_t)(bw * Ln + bi)) * Dn + tid];
        __syncthreads();
    }
}

// ---------------------------------------------------------------------------
static void run_bn(const float* x, const float* g, const float* b, float* y,
                   float* p_bnm, float* p_bninv, double* p_dpart, double* p_dmean)
{
    bnsum_k<<<200, 128>>>(x, p_dpart);
    bnmean_k<<<1, 128>>>(p_dpart, p_dmean, p_bnm);
    bnsq_k<<<200, 128>>>(x, p_dmean, p_dpart);
    bnvar_k<<<1, 128>>>(p_dpart, p_bninv);
    bnapply_k<<<(Mn * Dn) / 256, 256>>>(p_bnm, p_bninv, x, g, b, y, Mn * Dn);
}

extern "C" void kernel_launch(void* const* d_in, const int* in_sizes, int n_in,
                              void* d_out, int out_size)
{
    const float* inp     = (const float*)d_in[0];
    const float* w_in    = (const float*)d_in[1];
    const float* init_W  = (const float*)d_in[2];
    const float* init_b  = (const float*)d_in[3];
    const float* enc_Wq  = (const float*)d_in[4];
    const float* enc_Wk  = (const float*)d_in[5];
    const float* enc_Wv  = (const float*)d_in[6];
    const float* enc_Wo  = (const float*)d_in[7];
    const float* bn1_g   = (const float*)d_in[8];
    const float* bn1_b   = (const float*)d_in[9];
    const float* ff1_W   = (const float*)d_in[10];
    const float* ff1_b   = (const float*)d_in[11];
    const float* ff2_W   = (const float*)d_in[12];
    const float* ff2_b   = (const float*)d_in[13];
    const float* bn2_g   = (const float*)d_in[14];
    const float* bn2_b   = (const float*)d_in[15];
    const float* rn_emb_W = (const float*)d_in[16];
    const float* rn_emb_b = (const float*)d_in[17];
    const float* rn_out_W = (const float*)d_in[18];
    const float* rn_out_b = (const float*)d_in[19];
    const float* Wnode   = (const float*)d_in[20];
    const float* Wfixed  = (const float*)d_in[21];
    const float* Wstep   = (const float*)d_in[22];
    const float* Wout    = (const float*)d_in[23];

    float *p_h, *p_x, *p_qkv, *p_att, *p_ff, *p_mixed, *p_hWnode, *p_hWstep;
    float *p_mmean, *p_fixedW, *p_Wqkv, *p_bnm, *p_bninv, *p_coef;
    double *p_dpart, *p_dmean;
    cudaGetSymbolAddress((void**)&p_h, g_h);
    cudaGetSymbolAddress((void**)&p_x, g_x);
    cudaGetSymbolAddress((void**)&p_qkv, g_qkv);
    cudaGetSymbolAddress((void**)&p_att, g_att);
    cudaGetSymbolAddress((void**)&p_ff, g_ff);
    cudaGetSymbolAddress((void**)&p_mixed, g_mixed);
    cudaGetSymbolAddress((void**)&p_hWnode, g_hWnode);
    cudaGetSymbolAddress((void**)&p_hWstep, g_hWstep);
    cudaGetSymbolAddress((void**)&p_mmean, g_mmean);
    cudaGetSymbolAddress((void**)&p_fixedW, g_fixedW);
    cudaGetSymbolAddress((void**)&p_Wqkv, g_Wqkv);
    cudaGetSymbolAddress((void**)&p_bnm, g_bnm);
    cudaGetSymbolAddress((void**)&p_bninv, g_bninv);
    cudaGetSymbolAddress((void**)&p_coef, g_coef);
    cudaGetSymbolAddress((void**)&p_dpart, g_dpart);
    cudaGetSymbolAddress((void**)&p_dmean, g_dmean);

    cudaFuncSetAttribute(decode_k, cudaFuncAttributeMaxDynamicSharedMemorySize, SMEM_DECODE);

    // ---- encoder ----
    repack_k<<<(2 * Hn * Dn * DKn + 255) / 256, 256>>>(enc_Wq, enc_Wk, enc_Wv, p_Wqkv);
    init_k<<<Mn, 128>>>(inp, init_W, init_b, p_h);

    for (int l = 0; l < NLn; l++) {
        sgemm_k<<<dim3(384 / 128, Mn / 128), 256>>>(p_h, p_Wqkv + (size_t)l * Dn * 384,
                                                    nullptr, nullptr, p_qkv, Mn, 384, Dn, 0);
        attn_k<<<Bn * Hn, 256>>>(p_qkv, p_att);
        sgemm_k<<<dim3(Dn / 128, Mn / 128), 256>>>(p_att, enc_Wo + (size_t)l * Dn * Dn,
                                                   nullptr, p_h, p_x, Mn, Dn, Dn, 4);
        run_bn(p_x, bn1_g + l * Dn, bn1_b + l * Dn, p_h, p_bnm, p_bninv, p_dpart, p_dmean);
        sgemm_k<<<dim3(FFn / 128, Mn / 128), 256>>>(p_h, ff1_W + (size_t)l * Dn * FFn,
                                                    ff1_b + l * FFn, nullptr, p_ff,
                                                    Mn, FFn, Dn, 1 | 2);
        sgemm_k<<<dim3(Dn / 128, Mn / 128), 256>>>(p_ff, ff2_W + (size_t)l * FFn * Dn,
                                                   ff2_b + l * Dn, p_h, p_x,
                                                   Mn, Dn, FFn, 1 | 4);
        run_bn(p_x, bn2_g + l * Dn, bn2_b + l * Dn, p_h, p_bnm, p_bninv, p_dpart, p_dmean);
    }

    // ---- routing + mixing (literal) ----
    routing_k<<<1, 128>>>(w_in, rn_emb_W, rn_emb_b, rn_out_W, rn_out_b, p_coef);
    mixscale_k<<<MWn, 128>>>(p_h, p_coef, p_mixed);

    // ---- precompute per-bw ----
    sgemm_k<<<dim3(384 / 128, MWn / 128), 256>>>(p_mixed, Wnode, nullptr, nullptr, p_hWnode,
                                                 MWn, 384, Dn, 0);
    sgemm_k<<<dim3(Dn / 128, MWn / 128), 256>>>(p_mixed, Wstep, nullptr, nullptr, p_hWstep,
                                                MWn, Dn, Dn, 0);
    mmean_k<<<BWn, 128>>>(p_mixed, p_mmean);
    sgemm_k<<<dim3(Dn / 128, BWn / 128), 256>>>(p_mmean, Wfixed, nullptr, nullptr, p_fixedW,
                                                BWn, Dn, Dn, 0);

    // ---- decode ----
    const long long logSz = (long long)BWn * 200 * 200;
    const long long pisSz = (long long)BWn * 200;
    int writeLog = (out_size >= logSz) ? 1 : 0;
    long long pisOff = -1;
    if (out_size >= logSz + pisSz) pisOff = logSz;
    else if (!writeLog && out_size >= pisSz) pisOff = 0;

    decode_k<<<BWn, 256, SMEM_DECODE>>>(p_hWnode, p_hWstep, p_fixedW, Wout,
                                        (float*)d_out, writeLog, pisOff);
}

// round 14
// speedup vs baseline: 1.0554x; 1.0554x over previous
#include <cuda_runtime.h>
#include <cuda_bf16.h>
#include <math.h>
#include <stdint.h>

// Problem constants
#define Bn   128
#define Ln   200
#define Dn   128
#define Hn   8
#define DKn  16
#define FFn  512
#define NLn  2
#define NWn  3
#define Mn   (Bn*Ln)          // 25600
#define BWn  (Bn*NWn)         // 384
#define MWn  (BWn*Ln)         // 76800

typedef unsigned long long u64t;

// ---- packed f32x2 helpers (per-lane IEEE fp32) ----------------------------
__device__ __forceinline__ u64t pk2(float lo, float hi)
{
    u64t r; asm("mov.b64 %0, {%1,%2};" : "=l"(r) : "f"(lo), "f"(hi)); return r;
}
__device__ __forceinline__ float2 upk2(u64t v)
{
    float2 r; asm("mov.b64 {%0,%1}, %2;" : "=f"(r.x), "=f"(r.y) : "l"(v)); return r;
}
#define FMA2(d, a, b) \
    asm("fma.rn.f32x2 %0, %1, %2, %3;" : "=l"(d) : "l"(a), "l"(b), "l"(d))

// ---- XLA tanh replica (llvm_ir::EmitFastTanh, with_fma=true) --------------
__device__ __forceinline__ float xla_tanh(float x)
{
    float ax = fabsf(x);
    if (ax < 0.0004f) return x;
    const float clampv = 7.99881172180175781f;
    float xc = fminf(fmaxf(x, -clampv), clampv);
    float x2 = xc * xc;
    float p = fmaf(x2, -2.76076847742355e-16f, 2.00018790482477e-13f);
    p = fmaf(x2, p, -8.60467152213735e-11f);
    p = fmaf(x2, p, 5.12229709037114e-08f);
    p = fmaf(x2, p, 1.48572235717979e-05f);
    p = fmaf(x2, p, 6.37261928875436e-04f);
    p = fmaf(x2, p, 4.89352455891786e-03f);
    p = xc * p;
    float q = fmaf(x2, 1.19825839466702e-06f, 1.18534705686654e-04f);
    q = fmaf(x2, q, 2.26843463243900e-03f);
    q = fmaf(x2, q, 4.89352518554385e-03f);
    return p / q;
}

// ---------------- scratch (device globals; allocation-free) ----------------
__device__ float  g_h[Mn*Dn];
__device__ float  g_x[Mn*Dn];
__device__ float  g_qkv[Mn*384];
__device__ float  g_att[Mn*Dn];
__device__ float  g_ff[Mn*FFn];
__device__ float  g_mixed[MWn*Dn];
__device__ float  g_hWnode[MWn*384];
__device__ float  g_hWstep[MWn*Dn];
__device__ float  g_mmean[BWn*Dn];
__device__ float  g_fixedW[BWn*Dn];
__device__ float  g_Wqkv[2*Dn*384];
__device__ double g_dpart[200*128];
__device__ double g_dmean[128];
__device__ float  g_bnm[128];
__device__ float  g_bninv[128];
__device__ float  g_coef[4];

// ---------------- SGEMM 128x64 tile, 8x4 microtile, f32x2 FMA --------------
// (R12 version — conflict-free; measured fastest)
// flags: 1=+bias[n], 2=relu, 4=+res[m*N+n]
__global__ void __launch_bounds__(256) sgemm_k(
    const float* __restrict__ A, const float* __restrict__ B,
    const float* __restrict__ bias, const float* __restrict__ res,
    float* __restrict__ C, int M, int N, int K, int flags)
{
    __shared__ float As[16][130];
    __shared__ float Bs[16][64];
    int tid = threadIdx.x;
    int m0 = blockIdx.y * 128, n0 = blockIdx.x * 64;
    int ty = tid >> 4;
    int tx = tid & 15;
    u64t acc2[8][2] = {};
    for (int k0 = 0; k0 < K; k0 += 16) {
#pragma unroll
        for (int j = 0; j < 2; j++) {
            int f = tid + 256 * j;
            int row = f >> 2, c4 = (f & 3) << 2;
            float4 av = *(const float4*)&A[(size_t)(m0 + row) * K + k0 + c4];
            As[c4 + 0][row] = av.x; As[c4 + 1][row] = av.y;
            As[c4 + 2][row] = av.z; As[c4 + 3][row] = av.w;
        }
        {
            int brow = tid >> 4, bcol = (tid & 15) << 2;
            *(float4*)&Bs[brow][bcol] =
                *(const float4*)&B[(size_t)(k0 + brow) * N + n0 + bcol];
        }
        __syncthreads();
#pragma unroll
        for (int kk = 0; kk < 16; kk++) {
            float a[8];
#pragma unroll
            for (int i = 0; i < 8; i++) a[i] = As[kk][ty * 8 + i];
            u64t b01 = *(const u64t*)&Bs[kk][tx * 4];
            u64t b23 = *(const u64t*)&Bs[kk][tx * 4 + 2];
#pragma unroll
            for (int i = 0; i < 8; i++) {
                u64t aa = pk2(a[i], a[i]);
                FMA2(acc2[i][0], aa, b01);
                FMA2(acc2[i][1], aa, b23);
            }
        }
        __syncthreads();
    }
#pragma unroll
    for (int i = 0; i < 8; i++) {
        int m = m0 + ty * 8 + i;
        float2 v01 = upk2(acc2[i][0]);
        float2 v23 = upk2(acc2[i][1]);
        float vv[4] = {v01.x, v01.y, v23.x, v23.y};
#pragma unroll
        for (int j = 0; j < 4; j++) {
            int n = n0 + tx * 4 + j;
            float v = vv[j];
            if (flags & 1) v += bias[n];
            if (flags & 4) v += res[(size_t)m * N + n];
            if (flags & 2) v = fmaxf(v, 0.f);
            C[(size_t)m * N + n] = v;
        }
    }
}

// ---------------- weight repack: Wqkv[l][d][h*16+k] ------------------------
__global__ void repack_k(const float* __restrict__ Wq, const float* __restrict__ Wk,
                         const float* __restrict__ Wv, float* __restrict__ Wqkv)
{
    int i = blockIdx.x * blockDim.x + threadIdx.x;
    if (i >= 2 * Hn * Dn * DKn) return;
    int kk = i % DKn;
    int d  = (i / DKn) % Dn;
    int hh = (i / (DKn * Dn)) % Hn;
    int l  = i / (DKn * Dn * Hn);
    int src = ((l * Hn + hh) * Dn + d) * DKn + kk;
    float* o = Wqkv + (size_t)l * Dn * 384 + (size_t)d * 384;
    o[hh * 16 + kk]        = Wq[src];
    o[128 + hh * 16 + kk]  = Wk[src];
    o[256 + hh * 16 + kk]  = Wv[src];
}

// ---------------- init embed: h = input@init_W + init_b --------------------
__global__ void init_k(const float* __restrict__ inp, const float* __restrict__ W,
                       const float* __restrict__ bv, float* __restrict__ h)
{
    int m = blockIdx.x, d = threadIdx.x;
    float4 iv = *(const float4*)&inp[(size_t)m * 4];
    float s = iv.x * W[d];
    s = fmaf(iv.y, W[128 + d], s);
    s = fmaf(iv.z, W[256 + d], s);
    s = fmaf(iv.w, W[384 + d], s);
    h[(size_t)m * Dn + d] = s + bv[d];
}

// ---------------- encoder attention: padded smem, 2 CTAs/SM ----------------
__global__ void __launch_bounds__(256, 2) attn_k(const float* __restrict__ qkv,
                                                 float* __restrict__ outp)
{
    __shared__ float sq[Ln][17], sk[Ln][17], sv[Ln][17];
    int b = blockIdx.x >> 3, hh = blockIdx.x & 7;
    int tid = threadIdx.x, ln = tid & 31, wp = tid >> 5;
    for (int idx = tid; idx < Ln * 4; idx += 256) {
        int n = idx >> 2, k4 = (idx & 3) << 2;
        const float* row = qkv + ((size_t)(b * Ln + n)) * 384 + hh * 16 + k4;
        float4 q4 = *(const float4*)row;
        float4 k4v = *(const float4*)(row + 128);
        float4 v4 = *(const float4*)(row + 256);
        sq[n][k4 + 0] = q4.x; sq[n][k4 + 1] = q4.y; sq[n][k4 + 2] = q4.z; sq[n][k4 + 3] = q4.w;
        sk[n][k4 + 0] = k4v.x; sk[n][k4 + 1] = k4v.y; sk[n][k4 + 2] = k4v.z; sk[n][k4 + 3] = k4v.w;
        sv[n][k4 + 0] = v4.x; sv[n][k4 + 1] = v4.y; sv[n][k4 + 2] = v4.z; sv[n][k4 + 3] = v4.w;
    }
    __syncthreads();
    for (int n = wp; n < Ln; n += 8) {
        float qr[16];
#pragma unroll
        for (int kk = 0; kk < 16; kk++) qr[kk] = sq[n][kk];
        float sc[7]; float mx = -3.4e38f;
#pragma unroll
        for (int i = 0; i < 7; i++) {
            int m = ln + 32 * i;
            if (m < Ln) {
                float s = 0.f;
#pragma unroll
                for (int kk = 0; kk < 16; kk++) s = fmaf(qr[kk], sk[m][kk], s);
                s *= 0.25f; sc[i] = s; mx = fmaxf(mx, s);
            } else sc[i] = -3.4e38f;
        }
#pragma unroll
        for (int o = 16; o > 0; o >>= 1) mx = fmaxf(mx, __shfl_xor_sync(0xffffffffu, mx, o));
        float se = 0.f;
#pragma unroll
        for (int i = 0; i < 7; i++) {
            int m = ln + 32 * i;
            if (m < Ln) { sc[i] = expf(sc[i] - mx); se += sc[i]; }
        }
#pragma unroll
        for (int o = 16; o > 0; o >>= 1) se += __shfl_xor_sync(0xffffffffu, se, o);
        float inv = 1.f / se;
        float ps[7];
#pragma unroll
        for (int i = 0; i < 7; i++) ps[i] = sc[i] * inv;
#pragma unroll
        for (int kk = 0; kk < 16; kk++) {
            float a = 0.f;
#pragma unroll
            for (int i = 0; i < 7; i++) {
                int m = ln + 32 * i;
                if (m < Ln) a = fmaf(ps[i], sv[m][kk], a);
            }
#pragma unroll
            for (int o = 16; o > 0; o >>= 1) a += __shfl_xor_sync(0xffffffffu, a, o);
            if (ln == 0) outp[((size_t)(b * Ln + n)) * Dn + hh * 16 + kk] = a;
        }
    }
}

// ---------------- batch-norm: two-pass, double stats -----------------------
__global__ void bnsum_k(const float* __restrict__ x, double* __restrict__ part)
{
    int d = threadIdx.x; int blk = blockIdx.x;
    const float* p = x + (size_t)blk * 128 * Dn + d;
    double s = 0.0;
    for (int r = 0; r < 128; r++) s += (double)p[(size_t)r * Dn];
    part[blk * 128 + d] = s;
}
__global__ void bnmean_k(const double* __restrict__ part, double* __restrict__ dmean,
                         float* __restrict__ bnm)
{
    int d = threadIdx.x;
    double s = 0.0;
    for (int i = 0; i < 200; i++) s += part[i * 128 + d];
    double m = s / 25600.0;
    dmean[d] = m;
    bnm[d] = (float)m;
}
__global__ void bnsq_k(const float* __restrict__ x, const double* __restrict__ dmean,
                       double* __restrict__ part)
{
    int d = threadIdx.x; int blk = blockIdx.x;
    double m = dmean[d];
    const float* p = x + (size_t)blk * 128 * Dn + d;
    double s = 0.0;
    for (int r = 0; r < 128; r++) { double dv = (double)p[(size_t)r * Dn] - m; s += dv * dv; }
    part[blk * 128 + d] = s;
}
__global__ void bnvar_k(const double* __restrict__ part, float* __restrict__ bninv)
{
    int d = threadIdx.x;
    double s = 0.0;
    for (int i = 0; i < 200; i++) s += part[i * 128 + d];
    float var = (float)(s / 25600.0);
    bninv[d] = rsqrtf(var + 1e-5f);
}
__global__ void bnapply_k(const float* __restrict__ bnm, const float* __restrict__ bninv,
                          const float* __restrict__ x,
                          const float* __restrict__ g, const float* __restrict__ bb,
                          float* __restrict__ y, int total)
{
    int i = blockIdx.x * blockDim.x + threadIdx.x;
    if (i >= total) return;
    int d = i & 127;
    y[i] = (x[i] - bnm[d]) * bninv[d] * g[d] + bb[d];
}

// ---------------- routing net → coef ---------------------------------------
__global__ void routing_k(const float* __restrict__ w_in, const float* __restrict__ embW,
                          const float* __restrict__ embB, const float* __restrict__ outW,
                          const float* __restrict__ outB, float* __restrict__ coef)
{
    __shared__ double red[3][128];
    int d = threadIdx.x;
    for (int w = 0; w < NWn; w++) {
        float a = w_in[w * 2 + 0] * embW[d];
        a = fmaf(w_in[w * 2 + 1], embW[128 + d], a);
        a = a + embB[d];
        a = fmaxf(a, 0.f);
        red[w][d] = (double)a * (double)outW[d * 3];
    }
    __syncthreads();
    for (int s = 64; s > 0; s >>= 1) {
        if (d < s) for (int w = 0; w < NWn; w++) red[w][d] += red[w][d + s];
        __syncthreads();
    }
    if (d < NWn) {
        float v = (float)red[d][0] + outB[0] + w_in[d * 2 + 0];
        coef[d] = xla_tanh(v);
    }
}

// ---------------- mixed = coef_w * h ----------------------------------------
__global__ void mixscale_k(const float* __restrict__ h, const float* __restrict__ coef,
                           float* __restrict__ mixed)
{
    int row = blockIdx.x;
    int d = threadIdx.x;
    int bwIdx = row / Ln, n = row % Ln;
    int b = bwIdx / NWn, w = bwIdx % NWn;
    mixed[(size_t)row * Dn + d] = coef[w] * h[((size_t)(b * Ln + n)) * Dn + d];
}

// ---------------- mean over nodes of mixed ---------------------------------
__global__ void mmean_k(const float* __restrict__ mixed, float* __restrict__ mm)
{
    int bw = blockIdx.x, d = threadIdx.x;
    double s = 0.0;
    for (int n = 0; n < Ln; n++) s += (double)mixed[((size_t)(bw * Ln + n)) * Dn + d];
    mm[bw * Dn + d] = (float)(s / 200.0);
}

// ---------------- persistent decode: one CTA per bw, 2 CTAs/SM -------------
#define SMEM_DECODE ((25600 + 1600 + 128 + 512 + 200 + 128 + 128 + 128) * 4 + 224)

__global__ void __launch_bounds__(256, 2) decode_k(
    const float* __restrict__ hWnode, const float* __restrict__ hWstep,
    const float* __restrict__ fixedW, const float* __restrict__ Wout,
    float* __restrict__ out, int writeLog, long long pisOff)
{
    extern __shared__ float sm[];
    float* gKT    = sm;                 // [128][200] transposed gK
    float* scomp  = gKT + 128 * 200;    // [8][200] softmax probs
    float* sq     = scomp + 1600;       // [128] query
    float* spart  = sq + 128;           // [512] partials
    float* slog   = spart + 512;        // [200] logits (own buffer)
    float* sheads = slog + 200;         // [128]
    float* sglim  = sheads + 128;       // [128]
    float* sfix   = sglim + 128;        // [128]
    unsigned char* svis = (unsigned char*)(sfix + 128); // [200]
    float2* spart2  = (float2*)spart;
    float2* sheads2 = (float2*)sheads;
    float2* sglim2  = (float2*)sglim;

    const int bw = blockIdx.x;
    const int tid = threadIdx.x;
    const int ln = tid & 31, wp = tid >> 5;
    const float* gVg = hWnode + ((size_t)bw * Ln) * 384 + 128;   // gV rows, stride 384

    for (int idx = tid; idx < Ln * 32; idx += 256) {
        int n = idx >> 5, c4 = (idx & 31) << 2;
        const float* row = hWnode + ((size_t)(bw * Ln + n)) * 384;
        float4 kv = *(const float4*)(row + c4);
        gKT[(c4 + 0) * 200 + n] = kv.x;
        gKT[(c4 + 1) * 200 + n] = kv.y;
        gKT[(c4 + 2) * 200 + n] = kv.z;
        gKT[(c4 + 3) * 200 + n] = kv.w;
    }
    if (tid < 128) sfix[tid] = fixedW[bw * Dn + tid];
    for (int idx = tid; idx < 200; idx += 256) svis[idx] = 0;
    __syncthreads();
    // initial query (prev = 0)
    if (tid < 128)
        sq[tid] = sfix[tid] + hWstep[((size_t)(bw * Ln)) * Dn + tid];
    __syncthreads();

    for (int t = 0; t < Ln; t++) {
        // 1. compat + masked softmax: warp wp = head hh
        {
            int hh = wp;
            float qr[16];
#pragma unroll
            for (int kk = 0; kk < 16; kk++) qr[kk] = sq[hh * 16 + kk];
            float cv[7]; float mx = -3.4e38f;
#pragma unroll
            for (int i = 0; i < 7; i++) {
                int n = ln + 32 * i;
                float c;
                if (n < Ln) {
                    float s = 0.f;
#pragma unroll
                    for (int kk = 0; kk < 16; kk++)
                        s = fmaf(qr[kk], gKT[(hh * 16 + kk) * 200 + n], s);
                    s = s * 0.25f;
                    c = svis[n] ? -1e9f : s;
                    mx = fmaxf(mx, c);
                } else c = -3.4e38f;
                cv[i] = c;
            }
#pragma unroll
            for (int o = 16; o > 0; o >>= 1) mx = fmaxf(mx, __shfl_xor_sync(0xffffffffu, mx, o));
            float se = 0.f;
#pragma unroll
            for (int i = 0; i < 7; i++) {
                int n = ln + 32 * i;
                if (n < Ln) { cv[i] = expf(cv[i] - mx); se += cv[i]; }
            }
#pragma unroll
            for (int o = 16; o > 0; o >>= 1) se += __shfl_xor_sync(0xffffffffu, se, o);
#pragma unroll
            for (int i = 0; i < 7; i++) {
                int n = ln + 32 * i;
                if (n < Ln) scomp[hh * 200 + n] = cv[i] / se;
            }
        }
        __syncthreads();
        // 2. heads: 4-way n split, skip p==0 (bit-exact; saves load + FMA)
        {
            int cp = tid & 63, q = tid >> 6;
            int hh = cp >> 3;
            const float* p = &scomp[hh * 200];
            int nb = q * 50;
            const float* gvrow = gVg + (size_t)nb * 384 + 2 * cp;
            u64t acc0 = 0ull, acc1 = 0ull;
#pragma unroll 5
            for (int n = 0; n < 50; n += 2) {
                float p0 = p[nb + n], p1 = p[nb + n + 1];
                if (p0 != 0.f) {
                    u64t g0 = *(const u64t*)(gvrow + (size_t)n * 384);
                    FMA2(acc0, pk2(p0, p0), g0);
                }
                if (p1 != 0.f) {
                    u64t g1 = *(const u64t*)(gvrow + (size_t)(n + 1) * 384);
                    FMA2(acc1, pk2(p1, p1), g1);
                }
            }
            float2 a0 = upk2(acc0), a1 = upk2(acc1);
            spart2[q * 64 + cp] = make_float2(a0.x + a1.x, a0.y + a1.y);
        }
        __syncthreads();
        if (tid < 64) {
            float2 x0 = spart2[tid], x1 = spart2[64 + tid];
            float2 x2 = spart2[128 + tid], x3 = spart2[192 + tid];
            sheads2[tid] = make_float2((x0.x + x1.x) + (x2.x + x3.x),
                                       (x0.y + x1.y) + (x2.y + x3.y));
        }
        __syncthreads();
        // 3. glimpse = heads @ Wout: 4-way c split
        {
            int dp = tid & 63, q = tid >> 6;
            int cb = q * 32;
            u64t acc0 = 0ull, acc1 = 0ull;
#pragma unroll 4
            for (int c = 0; c < 32; c += 2) {
                float h0 = sheads[cb + c], h1 = sheads[cb + c + 1];
                u64t w0 = *(const u64t*)&Wout[(size_t)(cb + c) * 128 + 2 * dp];
                u64t w1 = *(const u64t*)&Wout[(size_t)(cb + c + 1) * 128 + 2 * dp];
                FMA2(acc0, pk2(h0, h0), w0);
                FMA2(acc1, pk2(h1, h1), w1);
            }
            float2 a0 = upk2(acc0), a1 = upk2(acc1);
            spart2[q * 64 + dp] = make_float2(a0.x + a1.x, a0.y + a1.y);
        }
        __syncthreads();
        if (tid < 64) {
            float2 x0 = spart2[tid], x1 = spart2[64 + tid];
            float2 x2 = spart2[128 + tid], x3 = spart2[192 + tid];
            sglim2[tid] = make_float2((x0.x + x1.x) + (x2.x + x3.x),
                                      (x0.y + x1.y) + (x2.y + x3.y));
        }
        __syncthreads();
        // 4. logits: 4 n per warp (8-lane groups); loads skipped for visited,
        //    shuffles UNCONDITIONAL (all 32 lanes; R11 deadlock lesson)
        {
            int grp = ln >> 3, li = ln & 7;
#pragma unroll
            for (int r = 0; r < 7; r++) {
                int n = r * 32 + wp * 4 + grp;          // warp-uniform n<Ln status
                if (n < Ln) {
                    float s = 0.f;
                    if (!svis[n]) {
                        const float* lk = hWnode + ((size_t)(bw * Ln + n)) * 384 + 256 + li * 16;
                        const float* gl = sglim + li * 16;
#pragma unroll
                        for (int j = 0; j < 4; j++) {
                            float4 kv = *(const float4*)(lk + 4 * j);
                            s = fmaf(gl[4 * j + 0], kv.x, s);
                            s = fmaf(gl[4 * j + 1], kv.y, s);
                            s = fmaf(gl[4 * j + 2], kv.z, s);
                            s = fmaf(gl[4 * j + 3], kv.w, s);
                        }
                    }
                    s += __shfl_xor_sync(0xffffffffu, s, 4);
                    s += __shfl_xor_sync(0xffffffffu, s, 2);
                    s += __shfl_xor_sync(0xffffffffu, s, 1);
                    if (li == 0)
                        slog[n] = svis[n] ? -1e9f
                                          : xla_tanh(s * 0.08838834764831843f) * 10.f;
                }
            }
        }
        __syncthreads();
        // 5. redundant per-warp LSE + argmax (identical in every warp)
        float mx, lg_se; int bi;
        {
            float vals[7]; mx = -3.4e38f;
#pragma unroll
            for (int i = 0; i < 7; i++) {
                int n = ln + 32 * i;
                float v = (n < Ln) ? slog[n] : -3.4e38f;
                vals[i] = v;
                mx = fmaxf(mx, v);
            }
#pragma unroll
            for (int o = 16; o > 0; o >>= 1) mx = fmaxf(mx, __shfl_xor_sync(0xffffffffu, mx, o));
            float se = 0.f;
#pragma unroll
            for (int i = 0; i < 7; i++) {
                int n = ln + 32 * i;
                if (n < Ln) se += expf(vals[i] - mx);
            }
#pragma unroll
            for (int o = 16; o > 0; o >>= 1) se += __shfl_xor_sync(0xffffffffu, se, o);
            lg_se = logf(se);
            float bv = -3.4e38f; bi = 0x7fffffff;
#pragma unroll
            for (int i = 0; i < 7; i++) {
                int n = ln + 32 * i;
                if (n < Ln) {
                    float lp = (vals[i] - mx) - lg_se;
                    if (lp > bv || (lp == bv && n < bi)) { bv = lp; bi = n; }
                }
            }
#pragma unroll
            for (int o = 16; o > 0; o >>= 1) {
                float ov = __shfl_xor_sync(0xffffffffu, bv, o);
                int   oi = __shfl_xor_sync(0xffffffffu, bi, o);
                if (ov > bv || (ov == bv && oi < bi)) { bv = ov; bi = oi; }
            }
        }
        // 6. immediate writes (no barrier: every thread has mx/lg_se/bi)
        if (tid == 0) {
            svis[bi] = 1;
            if (pisOff >= 0)
                out[(size_t)pisOff + (size_t)bw * 200 + t] = (float)bi;
        }
        if (writeLog) {
            size_t base = ((size_t)bw * 200 + t) * 200;
            for (int n = tid; n < Ln; n += 256)
                out[base + n] = (slog[n] - mx) - lg_se;
        }
        if (tid < 128)
            sq[tid] = sfix[tid] + hWstep[((size_t)(bw * Ln + bi)) * Dn + tid];
        __syncthreads();
    }
}

// ---------------------------------------------------------------------------
static void run_bn(const float* x, const float* g, const float* b, float* y,
                   float* p_bnm, float* p_bninv, double* p_dpart, double* p_dmean)
{
    bnsum_k<<<200, 128>>>(x, p_dpart);
    bnmean_k<<<1, 128>>>(p_dpart, p_dmean, p_bnm);
    bnsq_k<<<200, 128>>>(x, p_dmean, p_dpart);
    bnvar_k<<<1, 128>>>(p_dpart, p_bninv);
    bnapply_k<<<(Mn * Dn) / 256, 256>>>(p_bnm, p_bninv, x, g, b, y, Mn * Dn);
}

extern "C" void kernel_launch(void* const* d_in, const int* in_sizes, int n_in,
                              void* d_out, int out_size)
{
    const float* inp     = (const float*)d_in[0];
    const float* w_in    = (const float*)d_in[1];
    const float* init_W  = (const float*)d_in[2];
    const float* init_b  = (const float*)d_in[3];
    const float* enc_Wq  = (const float*)d_in[4];
    const float* enc_Wk  = (const float*)d_in[5];
    const float* enc_Wv  = (const float*)d_in[6];
    const float* enc_Wo  = (const float*)d_in[7];
    const float* bn1_g   = (const float*)d_in[8];
    const float* bn1_b   = (const float*)d_in[9];
    const float* ff1_W   = (const float*)d_in[10];
    const float* ff1_b   = (const float*)d_in[11];
    const float* ff2_W   = (const float*)d_in[12];
    const float* ff2_b   = (const float*)d_in[13];
    const float* bn2_g   = (const float*)d_in[14];
    const float* bn2_b   = (const float*)d_in[15];
    const float* rn_emb_W = (const float*)d_in[16];
    const float* rn_emb_b = (const float*)d_in[17];
    const float* rn_out_W = (const float*)d_in[18];
    const float* rn_out_b = (const float*)d_in[19];
    const float* Wnode   = (const float*)d_in[20];
    const float* Wfixed  = (const float*)d_in[21];
    const float* Wstep   = (const float*)d_in[22];
    const float* Wout    = (const float*)d_in[23];

    float *p_h, *p_x, *p_qkv, *p_att, *p_ff, *p_mixed, *p_hWnode, *p_hWstep;
    float *p_mmean, *p_fixedW, *p_Wqkv, *p_bnm, *p_bninv, *p_coef;
    double *p_dpart, *p_dmean;
    cudaGetSymbolAddress((void**)&p_h, g_h);
    cudaGetSymbolAddress((void**)&p_x, g_x);
    cudaGetSymbolAddress((void**)&p_qkv, g_qkv);
    cudaGetSymbolAddress((void**)&p_att, g_att);
    cudaGetSymbolAddress((void**)&p_ff, g_ff);
    cudaGetSymbolAddress((void**)&p_mixed, g_mixed);
    cudaGetSymbolAddress((void**)&p_hWnode, g_hWnode);
    cudaGetSymbolAddress((void**)&p_hWstep, g_hWstep);
    cudaGetSymbolAddress((void**)&p_mmean, g_mmean);
    cudaGetSymbolAddress((void**)&p_fixedW, g_fixedW);
    cudaGetSymbolAddress((void**)&p_Wqkv, g_Wqkv);
    cudaGetSymbolAddress((void**)&p_bnm, g_bnm);
    cudaGetSymbolAddress((void**)&p_bninv, g_bninv);
    cudaGetSymbolAddress((void**)&p_coef, g_coef);
    cudaGetSymbolAddress((void**)&p_dpart, g_dpart);
    cudaGetSymbolAddress((void**)&p_dmean, g_dmean);

    cudaFuncSetAttribute(decode_k, cudaFuncAttributeMaxDynamicSharedMemorySize, SMEM_DECODE);

    // ---- encoder ----
    repack_k<<<(2 * Hn * Dn * DKn + 255) / 256, 256>>>(enc_Wq, enc_Wk, enc_Wv, p_Wqkv);
    init_k<<<Mn, 128>>>(inp, init_W, init_b, p_h);

    for (int l = 0; l < NLn; l++) {
        sgemm_k<<<dim3(384 / 64, Mn / 128), 256>>>(p_h, p_Wqkv + (size_t)l * Dn * 384,
                                                   nullptr, nullptr, p_qkv, Mn, 384, Dn, 0);
        attn_k<<<Bn * Hn, 256>>>(p_qkv, p_att);
        sgemm_k<<<dim3(Dn / 64, Mn / 128), 256>>>(p_att, enc_Wo + (size_t)l * Dn * Dn,
                                                  nullptr, p_h, p_x, Mn, Dn, Dn, 4);
        run_bn(p_x, bn1_g + l * Dn, bn1_b + l * Dn, p_h, p_bnm, p_bninv, p_dpart, p_dmean);
        sgemm_k<<<dim3(FFn / 64, Mn / 128), 256>>>(p_h, ff1_W + (size_t)l * Dn * FFn,
                                                   ff1_b + l * FFn, nullptr, p_ff,
                                                   Mn, FFn, Dn, 1 | 2);
        sgemm_k<<<dim3(Dn / 64, Mn / 128), 256>>>(p_ff, ff2_W + (size_t)l * FFn * Dn,
                                                  ff2_b + l * Dn, p_h, p_x,
                                                  Mn, Dn, FFn, 1 | 4);
        run_bn(p_x, bn2_g + l * Dn, bn2_b + l * Dn, p_h, p_bnm, p_bninv, p_dpart, p_dmean);
    }

    // ---- routing + mixing (literal) ----
    routing_k<<<1, 128>>>(w_in, rn_emb_W, rn_emb_b, rn_out_W, rn_out_b, p_coef);
    mixscale_k<<<MWn, 128>>>(p_h, p_coef, p_mixed);

    // ---- precompute per-bw ----
    sgemm_k<<<dim3(384 / 64, MWn / 128), 256>>>(p_mixed, Wnode, nullptr, nullptr, p_hWnode,
                                                MWn, 384, Dn, 0);
    sgemm_k<<<dim3(Dn / 64, MWn / 128), 256>>>(p_mixed, Wstep, nullptr, nullptr, p_hWstep,
                                               MWn, Dn, Dn, 0);
    mmean_k<<<BWn, 128>>>(p_mixed, p_mmean);
    sgemm_k<<<dim3(Dn / 64, BWn / 128), 256>>>(p_mmean, Wfixed, nullptr, nullptr, p_fixedW,
                                               BWn, Dn, Dn, 0);

    // ---- decode ----
    const long long logSz = (long long)BWn * 200 * 200;
    const long long pisSz = (long long)BWn * 200;
    int writeLog = (out_size >= logSz) ? 1 : 0;
    long long pisOff = -1;
    if (out_size >= logSz + pisSz) pisOff = logSz;
    else if (!writeLog && out_size >= pisSz) pisOff = 0;

    decode_k<<<BWn, 256, SMEM_DECODE>>>(p_hWnode, p_hWstep, p_fixedW, Wout,
                                        (float*)d_out, writeLog, pisOff);
}

// round 15
// speedup vs baseline: 1.0861x; 1.0291x over previous
#include <cuda_runtime.h>
#include <cuda_bf16.h>
#include <math.h>
#include <stdint.h>

// Problem constants
#define Bn   128
#define Ln   200
#define Dn   128
#define Hn   8
#define DKn  16
#define FFn  512
#define NLn  2
#define NWn  3
#define Mn   (Bn*Ln)          // 25600
#define BWn  (Bn*NWn)         // 384
#define MWn  (BWn*Ln)         // 76800

typedef unsigned long long u64t;

// ---- packed f32x2 helpers (per-lane IEEE fp32) ----------------------------
__device__ __forceinline__ u64t pk2(float lo, float hi)
{
    u64t r; asm("mov.b64 %0, {%1,%2};" : "=l"(r) : "f"(lo), "f"(hi)); return r;
}
__device__ __forceinline__ float2 upk2(u64t v)
{
    float2 r; asm("mov.b64 {%0,%1}, %2;" : "=f"(r.x), "=f"(r.y) : "l"(v)); return r;
}
#define FMA2(d, a, b) \
    asm("fma.rn.f32x2 %0, %1, %2, %3;" : "=l"(d) : "l"(a), "l"(b), "l"(d))

// ---- XLA tanh replica (llvm_ir::EmitFastTanh, with_fma=true) --------------
__device__ __forceinline__ float xla_tanh(float x)
{
    float ax = fabsf(x);
    if (ax < 0.0004f) return x;
    const float clampv = 7.99881172180175781f;
    float xc = fminf(fmaxf(x, -clampv), clampv);
    float x2 = xc * xc;
    float p = fmaf(x2, -2.76076847742355e-16f, 2.00018790482477e-13f);
    p = fmaf(x2, p, -8.60467152213735e-11f);
    p = fmaf(x2, p, 5.12229709037114e-08f);
    p = fmaf(x2, p, 1.48572235717979e-05f);
    p = fmaf(x2, p, 6.37261928875436e-04f);
    p = fmaf(x2, p, 4.89352455891786e-03f);
    p = xc * p;
    float q = fmaf(x2, 1.19825839466702e-06f, 1.18534705686654e-04f);
    q = fmaf(x2, q, 2.26843463243900e-03f);
    q = fmaf(x2, q, 4.89352518554385e-03f);
    return p / q;
}

// ---------------- scratch (device globals; allocation-free) ----------------
__device__ float  g_h[Mn*Dn];
__device__ float  g_x[Mn*Dn];
__device__ float  g_qkv[Mn*384];
__device__ float  g_att[Mn*Dn];
__device__ float  g_ff[Mn*FFn];
__device__ float  g_mixed[MWn*Dn];
__device__ float  g_hWnode[MWn*384];
__device__ float  g_hWstep[MWn*Dn];
__device__ float  g_mmean[BWn*Dn];
__device__ float  g_fixedW[BWn*Dn];
__device__ float  g_Wqkv[2*Dn*384];
__device__ double g_dpart[200*256];
__device__ float  g_bnm[128];
__device__ float  g_bninv[128];
__device__ float  g_coef[4];

// ---------------- SGEMM 128x64 tile, 8x4 microtile, f32x2 FMA --------------
// (R12 version — conflict-free; measured fastest)
// flags: 1=+bias[n], 2=relu, 4=+res[m*N+n]
__global__ void __launch_bounds__(256) sgemm_k(
    const float* __restrict__ A, const float* __restrict__ B,
    const float* __restrict__ bias, const float* __restrict__ res,
    float* __restrict__ C, int M, int N, int K, int flags)
{
    __shared__ float As[16][130];
    __shared__ float Bs[16][64];
    int tid = threadIdx.x;
    int m0 = blockIdx.y * 128, n0 = blockIdx.x * 64;
    int ty = tid >> 4;
    int tx = tid & 15;
    u64t acc2[8][2] = {};
    for (int k0 = 0; k0 < K; k0 += 16) {
#pragma unroll
        for (int j = 0; j < 2; j++) {
            int f = tid + 256 * j;
            int row = f >> 2, c4 = (f & 3) << 2;
            float4 av = *(const float4*)&A[(size_t)(m0 + row) * K + k0 + c4];
            As[c4 + 0][row] = av.x; As[c4 + 1][row] = av.y;
            As[c4 + 2][row] = av.z; As[c4 + 3][row] = av.w;
        }
        {
            int brow = tid >> 4, bcol = (tid & 15) << 2;
            *(float4*)&Bs[brow][bcol] =
                *(const float4*)&B[(size_t)(k0 + brow) * N + n0 + bcol];
        }
        __syncthreads();
#pragma unroll
        for (int kk = 0; kk < 16; kk++) {
            float a[8];
#pragma unroll
            for (int i = 0; i < 8; i++) a[i] = As[kk][ty * 8 + i];
            u64t b01 = *(const u64t*)&Bs[kk][tx * 4];
            u64t b23 = *(const u64t*)&Bs[kk][tx * 4 + 2];
#pragma unroll
            for (int i = 0; i < 8; i++) {
                u64t aa = pk2(a[i], a[i]);
                FMA2(acc2[i][0], aa, b01);
                FMA2(acc2[i][1], aa, b23);
            }
        }
        __syncthreads();
    }
#pragma unroll
    for (int i = 0; i < 8; i++) {
        int m = m0 + ty * 8 + i;
        float2 v01 = upk2(acc2[i][0]);
        float2 v23 = upk2(acc2[i][1]);
        float vv[4] = {v01.x, v01.y, v23.x, v23.y};
#pragma unroll
        for (int j = 0; j < 4; j++) {
            int n = n0 + tx * 4 + j;
            float v = vv[j];
            if (flags & 1) v += bias[n];
            if (flags & 4) v += res[(size_t)m * N + n];
            if (flags & 2) v = fmaxf(v, 0.f);
            C[(size_t)m * N + n] = v;
        }
    }
}

// ---------------- weight repack: Wqkv[l][d][h*16+k] ------------------------
__global__ void repack_k(const float* __restrict__ Wq, const float* __restrict__ Wk,
                         const float* __restrict__ Wv, float* __restrict__ Wqkv)
{
    int i = blockIdx.x * blockDim.x + threadIdx.x;
    if (i >= 2 * Hn * Dn * DKn) return;
    int kk = i % DKn;
    int d  = (i / DKn) % Dn;
    int hh = (i / (DKn * Dn)) % Hn;
    int l  = i / (DKn * Dn * Hn);
    int src = ((l * Hn + hh) * Dn + d) * DKn + kk;
    float* o = Wqkv + (size_t)l * Dn * 384 + (size_t)d * 384;
    o[hh * 16 + kk]        = Wq[src];
    o[128 + hh * 16 + kk]  = Wk[src];
    o[256 + hh * 16 + kk]  = Wv[src];
}

// ---------------- init embed: h = input@init_W + init_b --------------------
__global__ void init_k(const float* __restrict__ inp, const float* __restrict__ W,
                       const float* __restrict__ bv, float* __restrict__ h)
{
    int m = blockIdx.x, d = threadIdx.x;
    float4 iv = *(const float4*)&inp[(size_t)m * 4];
    float s = iv.x * W[d];
    s = fmaf(iv.y, W[128 + d], s);
    s = fmaf(iv.z, W[256 + d], s);
    s = fmaf(iv.w, W[384 + d], s);
    h[(size_t)m * Dn + d] = s + bv[d];
}

// ---------------- encoder attention: padded smem, 2 CTAs/SM ----------------
__global__ void __launch_bounds__(256, 2) attn_k(const float* __restrict__ qkv,
                                                 float* __restrict__ outp)
{
    __shared__ float sq[Ln][17], sk[Ln][17], sv[Ln][17];
    int b = blockIdx.x >> 3, hh = blockIdx.x & 7;
    int tid = threadIdx.x, ln = tid & 31, wp = tid >> 5;
    for (int idx = tid; idx < Ln * 4; idx += 256) {
        int n = idx >> 2, k4 = (idx & 3) << 2;
        const float* row = qkv + ((size_t)(b * Ln + n)) * 384 + hh * 16 + k4;
        float4 q4 = *(const float4*)row;
        float4 k4v = *(const float4*)(row + 128);
        float4 v4 = *(const float4*)(row + 256);
        sq[n][k4 + 0] = q4.x; sq[n][k4 + 1] = q4.y; sq[n][k4 + 2] = q4.z; sq[n][k4 + 3] = q4.w;
        sk[n][k4 + 0] = k4v.x; sk[n][k4 + 1] = k4v.y; sk[n][k4 + 2] = k4v.z; sk[n][k4 + 3] = k4v.w;
        sv[n][k4 + 0] = v4.x; sv[n][k4 + 1] = v4.y; sv[n][k4 + 2] = v4.z; sv[n][k4 + 3] = v4.w;
    }
    __syncthreads();
    for (int n = wp; n < Ln; n += 8) {
        float qr[16];
#pragma unroll
        for (int kk = 0; kk < 16; kk++) qr[kk] = sq[n][kk];
        float sc[7]; float mx = -3.4e38f;
#pragma unroll
        for (int i = 0; i < 7; i++) {
            int m = ln + 32 * i;
            if (m < Ln) {
                float s = 0.f;
#pragma unroll
                for (int kk = 0; kk < 16; kk++) s = fmaf(qr[kk], sk[m][kk], s);
                s *= 0.25f; sc[i] = s; mx = fmaxf(mx, s);
            } else sc[i] = -3.4e38f;
        }
#pragma unroll
        for (int o = 16; o > 0; o >>= 1) mx = fmaxf(mx, __shfl_xor_sync(0xffffffffu, mx, o));
        float se = 0.f;
#pragma unroll
        for (int i = 0; i < 7; i++) {
            int m = ln + 32 * i;
            if (m < Ln) { sc[i] = expf(sc[i] - mx); se += sc[i]; }
        }
#pragma unroll
        for (int o = 16; o > 0; o >>= 1) se += __shfl_xor_sync(0xffffffffu, se, o);
        float inv = 1.f / se;
        float ps[7];
#pragma unroll
        for (int i = 0; i < 7; i++) ps[i] = sc[i] * inv;
#pragma unroll
        for (int kk = 0; kk < 16; kk++) {
            float a = 0.f;
#pragma unroll
            for (int i = 0; i < 7; i++) {
                int m = ln + 32 * i;
                if (m < Ln) a = fmaf(ps[i], sv[m][kk], a);
            }
#pragma unroll
            for (int o = 16; o > 0; o >>= 1) a += __shfl_xor_sync(0xffffffffu, a, o);
            if (ln == 0) outp[((size_t)(b * Ln + n)) * Dn + hh * 16 + kk] = a;
        }
    }
}

// ---------------- batch-norm: fused single-pass stats (double) -------------
__global__ void bnstats_k(const float* __restrict__ x, double* __restrict__ part)
{
    int d = threadIdx.x; int blk = blockIdx.x;
    const float* p = x + (size_t)blk * 128 * Dn + d;
    double s = 0.0, s2 = 0.0;
    for (int r = 0; r < 128; r++) {
        double v = (double)p[(size_t)r * Dn];
        s += v; s2 += v * v;
    }
    part[blk * 256 + d] = s;
    part[blk * 256 + 128 + d] = s2;
}
__global__ void bnfinal_k(const double* __restrict__ part,
                          float* __restrict__ bnm, float* __restrict__ bninv)
{
    int d = threadIdx.x;
    double s = 0.0, s2 = 0.0;
    for (int i = 0; i < 200; i++) {
        s  += part[i * 256 + d];
        s2 += part[i * 256 + 128 + d];
    }
    double m = s / 25600.0;
    double var = s2 / 25600.0 - m * m;
    bnm[d] = (float)m;
    bninv[d] = rsqrtf((float)var + 1e-5f);
}
__global__ void bnapply_k(const float* __restrict__ bnm, const float* __restrict__ bninv,
                          const float* __restrict__ x,
                          const float* __restrict__ g, const float* __restrict__ bb,
                          float* __restrict__ y, int total)
{
    int i = blockIdx.x * blockDim.x + threadIdx.x;
    if (i >= total) return;
    int d = i & 127;
    y[i] = (x[i] - bnm[d]) * bninv[d] * g[d] + bb[d];
}

// ---------------- routing net → coef ---------------------------------------
__global__ void routing_k(const float* __restrict__ w_in, const float* __restrict__ embW,
                          const float* __restrict__ embB, const float* __restrict__ outW,
                          const float* __restrict__ outB, float* __restrict__ coef)
{
    __shared__ double red[3][128];
    int d = threadIdx.x;
    for (int w = 0; w < NWn; w++) {
        float a = w_in[w * 2 + 0] * embW[d];
        a = fmaf(w_in[w * 2 + 1], embW[128 + d], a);
        a = a + embB[d];
        a = fmaxf(a, 0.f);
        red[w][d] = (double)a * (double)outW[d * 3];
    }
    __syncthreads();
    for (int s = 64; s > 0; s >>= 1) {
        if (d < s) for (int w = 0; w < NWn; w++) red[w][d] += red[w][d + s];
        __syncthreads();
    }
    if (d < NWn) {
        float v = (float)red[d][0] + outB[0] + w_in[d * 2 + 0];
        coef[d] = xla_tanh(v);
    }
}

// ---------------- mixed = coef_w * h ----------------------------------------
__global__ void mixscale_k(const float* __restrict__ h, const float* __restrict__ coef,
                           float* __restrict__ mixed)
{
    int row = blockIdx.x;
    int d = threadIdx.x;
    int bwIdx = row / Ln, n = row % Ln;
    int b = bwIdx / NWn, w = bwIdx % NWn;
    mixed[(size_t)row * Dn + d] = coef[w] * h[((size_t)(b * Ln + n)) * Dn + d];
}

// ---------------- mean over nodes of mixed ---------------------------------
__global__ void mmean_k(const float* __restrict__ mixed, float* __restrict__ mm)
{
    int bw = blockIdx.x, d = threadIdx.x;
    double s = 0.0;
    for (int n = 0; n < Ln; n++) s += (double)mixed[((size_t)(bw * Ln + n)) * Dn + d];
    mm[bw * Dn + d] = (float)(s / 200.0);
}

// ---------------- persistent decode: one CTA per bw, 2 CTAs/SM -------------
// floats: gKT 25600 | scomp 1600 | sq 128 | spartBig 1024 (slog overlays)
//         sheads 128 | sglim 128 | sfix 128  + svis bytes
#define SMEM_DECODE ((25600 + 1600 + 128 + 1024 + 128 + 128 + 128) * 4 + 224)

__global__ void __launch_bounds__(256, 2) decode_k(
    const float* __restrict__ hWnode, const float* __restrict__ hWstep,
    const float* __restrict__ fixedW, const float* __restrict__ Wout,
    float* __restrict__ out, int writeLog, long long pisOff)
{
    extern __shared__ float sm[];
    float* gKT      = sm;                 // [128][200]
    float* scomp    = gKT + 128 * 200;    // [8][200]
    float* sq       = scomp + 1600;       // [128]
    float* spartBig = sq + 128;           // [8][128]; slog aliases first 200
    float* slog     = spartBig;           // [200] (phase-disjoint w/ spartBig)
    float* sheads   = spartBig + 1024;    // [128]
    float* sglim    = sheads + 128;       // [128]
    float* sfix     = sglim + 128;        // [128]
    unsigned char* svis = (unsigned char*)(sfix + 128); // [200]

    const int bw = blockIdx.x;
    const int tid = threadIdx.x;
    const int ln = tid & 31, wp = tid >> 5;
    const float* gVg = hWnode + ((size_t)bw * Ln) * 384 + 128;

    for (int idx = tid; idx < Ln * 32; idx += 256) {
        int n = idx >> 5, c4 = (idx & 31) << 2;
        const float* row = hWnode + ((size_t)(bw * Ln + n)) * 384;
        float4 kv = *(const float4*)(row + c4);
        gKT[(c4 + 0) * 200 + n] = kv.x;
        gKT[(c4 + 1) * 200 + n] = kv.y;
        gKT[(c4 + 2) * 200 + n] = kv.z;
        gKT[(c4 + 3) * 200 + n] = kv.w;
    }
    if (tid < 128) sfix[tid] = fixedW[bw * Dn + tid];
    for (int idx = tid; idx < 200; idx += 256) svis[idx] = 0;
    __syncthreads();
    if (tid < 128)
        sq[tid] = sfix[tid] + hWstep[((size_t)(bw * Ln)) * Dn + tid];
    __syncthreads();

    for (int t = 0; t < Ln; t++) {
        // 1. compat + masked softmax: warp wp = head hh
        {
            int hh = wp;
            float qr[16];
#pragma unroll
            for (int kk = 0; kk < 16; kk++) qr[kk] = sq[hh * 16 + kk];
            float cv[7]; float mx = -3.4e38f;
#pragma unroll
            for (int i = 0; i < 7; i++) {
                int n = ln + 32 * i;
                float c;
                if (n < Ln) {
                    float s = 0.f;
#pragma unroll
                    for (int kk = 0; kk < 16; kk++)
                        s = fmaf(qr[kk], gKT[(hh * 16 + kk) * 200 + n], s);
                    s = s * 0.25f;
                    c = svis[n] ? -1e9f : s;
                    mx = fmaxf(mx, c);
                } else c = -3.4e38f;
                cv[i] = c;
            }
#pragma unroll
            for (int o = 16; o > 0; o >>= 1) mx = fmaxf(mx, __shfl_xor_sync(0xffffffffu, mx, o));
            float se = 0.f;
#pragma unroll
            for (int i = 0; i < 7; i++) {
                int n = ln + 32 * i;
                if (n < Ln) { cv[i] = expf(cv[i] - mx); se += cv[i]; }
            }
#pragma unroll
            for (int o = 16; o > 0; o >>= 1) se += __shfl_xor_sync(0xffffffffu, se, o);
#pragma unroll
            for (int i = 0; i < 7; i++) {
                int n = ln + 32 * i;
                if (n < Ln) scomp[hh * 200 + n] = cv[i] / se;
            }
        }
        __syncthreads();
        // 2. heads: 8-way n split, float4 gV loads, unconditional FMA
        {
            int c4 = (tid & 31) * 4;     // channel base
            int q = tid >> 5;            // n-block 0..7
            int hh = c4 >> 4;
            const float* p = &scomp[hh * 200];
            int nb = q * 25;
            const float* gvrow = gVg + (size_t)nb * 384 + c4;
            u64t acc0 = 0ull, acc1 = 0ull;
#pragma unroll 5
            for (int n = 0; n < 25; n++) {
                float pn = p[nb + n];
                float4 g = *(const float4*)(gvrow + (size_t)n * 384);
                u64t pp = pk2(pn, pn);
                FMA2(acc0, pp, pk2(g.x, g.y));
                FMA2(acc1, pp, pk2(g.z, g.w));
            }
            float2 a0 = upk2(acc0), a1 = upk2(acc1);
            *(float4*)&spartBig[q * 128 + c4] = make_float4(a0.x, a0.y, a1.x, a1.y);
        }
        __syncthreads();
        if (tid < 128) {
            float s = 0.f;
#pragma unroll
            for (int q = 0; q < 8; q++) s += spartBig[q * 128 + tid];
            sheads[tid] = s;
        }
        __syncthreads();
        // 3. glimpse = heads @ Wout: float4 loads, 8-way c split
        {
            int d4 = (tid & 31) * 4;
            int q = tid >> 5;
            int cb = q * 16;
            u64t acc0 = 0ull, acc1 = 0ull;
#pragma unroll 4
            for (int c = 0; c < 16; c++) {
                float hv = sheads[cb + c];
                float4 w = *(const float4*)&Wout[(size_t)(cb + c) * 128 + d4];
                u64t hh2 = pk2(hv, hv);
                FMA2(acc0, hh2, pk2(w.x, w.y));
                FMA2(acc1, hh2, pk2(w.z, w.w));
            }
            float2 a0 = upk2(acc0), a1 = upk2(acc1);
            *(float4*)&spartBig[q * 128 + d4] = make_float4(a0.x, a0.y, a1.x, a1.y);
        }
        __syncthreads();
        if (tid < 128) {
            float s = 0.f;
#pragma unroll
            for (int q = 0; q < 8; q++) s += spartBig[q * 128 + tid];
            sglim[tid] = s;
        }
        __syncthreads();
        // 4a. logits dots: all loads/FMA first (no sync ops), 8-lane groups
        int grp = ln >> 3, li = ln & 7;
        float sarr[7];
#pragma unroll
        for (int r = 0; r < 7; r++) {
            int n = r * 32 + wp * 4 + grp;
            float s = 0.f;
            if (n < Ln && !svis[n]) {
                const float* lk = hWnode + ((size_t)(bw * Ln + n)) * 384 + 256 + li * 16;
                const float* gl = sglim + li * 16;
#pragma unroll
                for (int j = 0; j < 4; j++) {
                    float4 kv = *(const float4*)(lk + 4 * j);
                    s = fmaf(gl[4 * j + 0], kv.x, s);
                    s = fmaf(gl[4 * j + 1], kv.y, s);
                    s = fmaf(gl[4 * j + 2], kv.z, s);
                    s = fmaf(gl[4 * j + 3], kv.w, s);
                }
            }
            sarr[r] = s;
        }
        // 4b. shuffle reductions (unconditional; all 32 lanes)
#pragma unroll
        for (int r = 0; r < 7; r++) {
            int n = r * 32 + wp * 4 + grp;
            float s = sarr[r];
            s += __shfl_xor_sync(0xffffffffu, s, 4);
            s += __shfl_xor_sync(0xffffffffu, s, 2);
            s += __shfl_xor_sync(0xffffffffu, s, 1);
            if (n < Ln && li == 0)
                slog[n] = svis[n] ? -1e9f
                                  : xla_tanh(s * 0.08838834764831843f) * 10.f;
        }
        __syncthreads();
        // 5. redundant per-warp LSE + argmax (identical in every warp)
        float mx, lg_se; int bi;
        {
            float vals[7]; mx = -3.4e38f;
#pragma unroll
            for (int i = 0; i < 7; i++) {
                int n = ln + 32 * i;
                float v = (n < Ln) ? slog[n] : -3.4e38f;
                vals[i] = v;
                mx = fmaxf(mx, v);
            }
#pragma unroll
            for (int o = 16; o > 0; o >>= 1) mx = fmaxf(mx, __shfl_xor_sync(0xffffffffu, mx, o));
            float se = 0.f;
#pragma unroll
            for (int i = 0; i < 7; i++) {
                int n = ln + 32 * i;
                if (n < Ln) se += expf(vals[i] - mx);
            }
#pragma unroll
            for (int o = 16; o > 0; o >>= 1) se += __shfl_xor_sync(0xffffffffu, se, o);
            lg_se = logf(se);
            float bv = -3.4e38f; bi = 0x7fffffff;
#pragma unroll
            for (int i = 0; i < 7; i++) {
                int n = ln + 32 * i;
                if (n < Ln) {
                    float lp = (vals[i] - mx) - lg_se;
                    if (lp > bv || (lp == bv && n < bi)) { bv = lp; bi = n; }
                }
            }
#pragma unroll
            for (int o = 16; o > 0; o >>= 1) {
                float ov = __shfl_xor_sync(0xffffffffu, bv, o);
                int   oi = __shfl_xor_sync(0xffffffffu, bi, o);
                if (ov > bv || (ov == bv && oi < bi)) { bv = ov; bi = oi; }
            }
        }
        // 6. immediate writes (no barrier: every thread has mx/lg_se/bi)
        if (tid == 0) {
            svis[bi] = 1;
            if (pisOff >= 0)
                out[(size_t)pisOff + (size_t)bw * 200 + t] = (float)bi;
        }
        if (writeLog) {
            size_t base = ((size_t)bw * 200 + t) * 200;
            for (int n = tid; n < Ln; n += 256)
                out[base + n] = (slog[n] - mx) - lg_se;
        }
        if (tid < 128)
            sq[tid] = sfix[tid] + hWstep[((size_t)(bw * Ln + bi)) * Dn + tid];
        __syncthreads();
    }
}

// ---------------------------------------------------------------------------
static void run_bn(const float* x, const float* g, const float* b, float* y,
                   float* p_bnm, float* p_bninv, double* p_dpart)
{
    bnstats_k<<<200, 128>>>(x, p_dpart);
    bnfinal_k<<<1, 128>>>(p_dpart, p_bnm, p_bninv);
    bnapply_k<<<(Mn * Dn) / 256, 256>>>(p_bnm, p_bninv, x, g, b, y, Mn * Dn);
}

extern "C" void kernel_launch(void* const* d_in, const int* in_sizes, int n_in,
                              void* d_out, int out_size)
{
    const float* inp     = (const float*)d_in[0];
    const float* w_in    = (const float*)d_in[1];
    const float* init_W  = (const float*)d_in[2];
    const float* init_b  = (const float*)d_in[3];
    const float* enc_Wq  = (const float*)d_in[4];
    const float* enc_Wk  = (const float*)d_in[5];
    const float* enc_Wv  = (const float*)d_in[6];
    const float* enc_Wo  = (const float*)d_in[7];
    const float* bn1_g   = (const float*)d_in[8];
    const float* bn1_b   = (const float*)d_in[9];
    const float* ff1_W   = (const float*)d_in[10];
    const float* ff1_b   = (const float*)d_in[11];
    const float* ff2_W   = (const float*)d_in[12];
    const float* ff2_b   = (const float*)d_in[13];
    const float* bn2_g   = (const float*)d_in[14];
    const float* bn2_b   = (const float*)d_in[15];
    const float* rn_emb_W = (const float*)d_in[16];
    const float* rn_emb_b = (const float*)d_in[17];
    const float* rn_out_W = (const float*)d_in[18];
    const float* rn_out_b = (const float*)d_in[19];
    const float* Wnode   = (const float*)d_in[20];
    const float* Wfixed  = (const float*)d_in[21];
    const float* Wstep   = (const float*)d_in[22];
    const float* Wout    = (const float*)d_in[23];

    float *p_h, *p_x, *p_qkv, *p_att, *p_ff, *p_mixed, *p_hWnode, *p_hWstep;
    float *p_mmean, *p_fixedW, *p_Wqkv, *p_bnm, *p_bninv, *p_coef;
    double *p_dpart;
    cudaGetSymbolAddress((void**)&p_h, g_h);
    cudaGetSymbolAddress((void**)&p_x, g_x);
    cudaGetSymbolAddress((void**)&p_qkv, g_qkv);
    cudaGetSymbolAddress((void**)&p_att, g_att);
    cudaGetSymbolAddress((void**)&p_ff, g_ff);
    cudaGetSymbolAddress((void**)&p_mixed, g_mixed);
    cudaGetSymbolAddress((void**)&p_hWnode, g_hWnode);
    cudaGetSymbolAddress((void**)&p_hWstep, g_hWstep);
    cudaGetSymbolAddress((void**)&p_mmean, g_mmean);
    cudaGetSymbolAddress((void**)&p_fixedW, g_fixedW);
    cudaGetSymbolAddress((void**)&p_Wqkv, g_Wqkv);
    cudaGetSymbolAddress((void**)&p_bnm, g_bnm);
    cudaGetSymbolAddress((void**)&p_bninv, g_bninv);
    cudaGetSymbolAddress((void**)&p_coef, g_coef);
    cudaGetSymbolAddress((void**)&p_dpart, g_dpart);

    cudaFuncSetAttribute(decode_k, cudaFuncAttributeMaxDynamicSharedMemorySize, SMEM_DECODE);

    // ---- encoder ----
    repack_k<<<(2 * Hn * Dn * DKn + 255) / 256, 256>>>(enc_Wq, enc_Wk, enc_Wv, p_Wqkv);
    init_k<<<Mn, 128>>>(inp, init_W, init_b, p_h);

    for (int l = 0; l < NLn; l++) {
        sgemm_k<<<dim3(384 / 64, Mn / 128), 256>>>(p_h, p_Wqkv + (size_t)l * Dn * 384,
                                                   nullptr, nullptr, p_qkv, Mn, 384, Dn, 0);
        attn_k<<<Bn * Hn, 256>>>(p_qkv, p_att);
        sgemm_k<<<dim3(Dn / 64, Mn / 128), 256>>>(p_att, enc_Wo + (size_t)l * Dn * Dn,
                                                  nullptr, p_h, p_x, Mn, Dn, Dn, 4);
        run_bn(p_x, bn1_g + l * Dn, bn1_b + l * Dn, p_h, p_bnm, p_bninv, p_dpart);
        sgemm_k<<<dim3(FFn / 64, Mn / 128), 256>>>(p_h, ff1_W + (size_t)l * Dn * FFn,
                                                   ff1_b + l * FFn, nullptr, p_ff,
                                                   Mn, FFn, Dn, 1 | 2);
        sgemm_k<<<dim3(Dn / 64, Mn / 128), 256>>>(p_ff, ff2_W + (size_t)l * FFn * Dn,
                                                  ff2_b + l * Dn, p_h, p_x,
                                                  Mn, Dn, FFn, 1 | 4);
        run_bn(p_x, bn2_g + l * Dn, bn2_b + l * Dn, p_h, p_bnm, p_bninv, p_dpart);
    }

    // ---- routing + mixing (literal) ----
    routing_k<<<1, 128>>>(w_in, rn_emb_W, rn_emb_b, rn_out_W, rn_out_b, p_coef);
    mixscale_k<<<MWn, 128>>>(p_h, p_coef, p_mixed);

    // ---- precompute per-bw ----
    sgemm_k<<<dim3(384 / 64, MWn / 128), 256>>>(p_mixed, Wnode, nullptr, nullptr, p_hWnode,
                                                MWn, 384, Dn, 0);
    sgemm_k<<<dim3(Dn / 64, MWn / 128), 256>>>(p_mixed, Wstep, nullptr, nullptr, p_hWstep,
                                               MWn, Dn, Dn, 0);
    mmean_k<<<BWn, 128>>>(p_mixed, p_mmean);
    sgemm_k<<<dim3(Dn / 64, BWn / 128), 256>>>(p_mmean, Wfixed, nullptr, nullptr, p_fixedW,
                                               BWn, Dn, Dn, 0);

    // ---- decode ----
    const long long logSz = (long long)BWn * 200 * 200;
    const long long pisSz = (long long)BWn * 200;
    int writeLog = (out_size >= logSz) ? 1 : 0;
    long long pisOff = -1;
    if (out_size >= logSz + pisSz) pisOff = logSz;
    else if (!writeLog && out_size >= pisSz) pisOff = 0;

    decode_k<<<BWn, 256, SMEM_DECODE>>>(p_hWnode, p_hWstep, p_fixedW, Wout,
                                        (float*)d_out, writeLog, pisOff);
}